// round 15
// baseline (speedup 1.0000x reference)
#include <cuda_runtime.h>
#include <cuda_bf16.h>
#include <cstdint>

#define DEV_INLINE __device__ __forceinline__
typedef unsigned long long u64;
typedef uint32_t u32;

constexpr int B_ = 8;
constexpr int C_ = 256;
constexpr int CI = 32;
constexpr int N_ = 4096;
constexpr int NSPL = 4;    // k3 split
constexpr int NSPL2 = 8;   // k2 split (partials are tiny)
constexpr float L2E = 1.4426950408889634f;
constexpr int STR = 144;   // smem operand row stride (bytes)

__device__ __align__(128) float g_alpha[B_ * N_];
__device__ __align__(128) float g_wAll[C_ * 96];
__device__ __align__(128) float g_part[NSPL * B_ * CI * N_];
__device__ __align__(128) float2 g_mz[NSPL2 * B_ * N_];
__device__ __align__(128) __nv_bfloat16 g_y1b[(size_t)B_ * N_ * 64];  // [pos][32hi|32lo]
__device__ __align__(128) __nv_bfloat16 g_y2b[(size_t)B_ * N_ * 64];  // pre-scaled log2e
__device__ __align__(128) __nv_bfloat16 g_y3h[(size_t)B_ * CI * N_];  // [ci][n] hi

DEV_INLINE float fexp2(float v) { float y; asm("ex2.approx.ftz.f32 %0, %1;" : "=f"(y) : "f"(v)); return y; }
DEV_INLINE float flog2(float v) { float y; asm("lg2.approx.ftz.f32 %0, %1;" : "=f"(y) : "f"(v)); return y; }
DEV_INLINE float frcp(float v)  { float y; asm("rcp.approx.ftz.f32 %0, %1;" : "=f"(y) : "f"(v)); return y; }
DEV_INLINE u64 pack2(float lo, float hi) {
    u64 r; asm("mov.b64 %0, {%1,%2};" : "=l"(r) : "r"(__float_as_uint(lo)), "r"(__float_as_uint(hi)));
    return r;
}
DEV_INLINE void unpack2(u64 v, float& lo, float& hi) {
    unsigned a, b; asm("mov.b64 {%0,%1}, %2;" : "=r"(a), "=r"(b) : "l"(v));
    lo = __uint_as_float(a); hi = __uint_as_float(b);
}
DEV_INLINE u64 fma2(u64 a, u64 b, u64 c) {
    u64 d; asm("fma.rn.f32x2 %0, %1, %2, %3;" : "=l"(d) : "l"(a), "l"(b), "l"(c));
    return d;
}
DEV_INLINE void split2(float2 f, unsigned& h, unsigned& l) {
    __nv_bfloat162 hb = __float22bfloat162_rn(f);
    h = *(unsigned*)&hb;
    float2 hf = __bfloat1622float2(hb);
    __nv_bfloat162 lb = __float22bfloat162_rn(make_float2(f.x - hf.x, f.y - hf.y));
    l = *(unsigned*)&lb;
}
DEV_INLINE u32 smem_u32(const void* p) {
    u32 a; asm("{ .reg .u64 t; cvta.to.shared.u64 t, %1; cvt.u32.u64 %0, t; }" : "=r"(a) : "l"(p));
    return a;
}
DEV_INLINE void ldsm4(u32* r, u32 a) {
    asm volatile("ldmatrix.sync.aligned.m8n8.x4.shared.b16 {%0,%1,%2,%3}, [%4];"
                 : "=r"(r[0]), "=r"(r[1]), "=r"(r[2]), "=r"(r[3]) : "r"(a));
}
DEV_INLINE void ldsm2(u32* r, u32 a) {
    asm volatile("ldmatrix.sync.aligned.m8n8.x2.shared.b16 {%0,%1}, [%2];"
                 : "=r"(r[0]), "=r"(r[1]) : "r"(a));
}
DEV_INLINE void mma16816(float* d, const u32* a, const u32* b) {
    asm volatile("mma.sync.aligned.m16n8k16.row.col.f32.bf16.bf16.f32 "
        "{%0,%1,%2,%3},{%4,%5,%6,%7},{%8,%9},{%0,%1,%2,%3};"
        : "+f"(d[0]), "+f"(d[1]), "+f"(d[2]), "+f"(d[3])
        : "r"(a[0]), "r"(a[1]), "r"(a[2]), "r"(a[3]), "r"(b[0]), "r"(b[1]));
}
DEV_INLINE u32 cvt2(float lo, float hi) {
    u32 r; asm("cvt.rn.bf16x2.f32 %0, %1, %2;" : "=r"(r) : "f"(hi), "f"(lo));
    return r;
}
DEV_INLINE float lo_f(u32 h) { return __uint_as_float(h << 16); }
DEV_INLINE float hi_f(u32 h) { return __uint_as_float(h & 0xffff0000u); }

DEV_INLINE void load_afrags(u32 base, int w, int L, u32 Ah[2][2][4], u32 Al[2][2][4]) {
#pragma unroll
    for (int mb = 0; mb < 2; mb++) {
        u32 a = base + (u32)((w * 32 + mb * 16 + (L & 15)) * STR) + (u32)((L >> 4) * 16);
#pragma unroll
        for (int k = 0; k < 2; k++) {
            ldsm4(Ah[mb][k], a + k * 32);
            ldsm4(Al[mb][k], a + 64 + k * 32);
        }
    }
}

// ---------------------------------------------------------------------------
__global__ void k0_prep(const float* __restrict__ w1, const float* __restrict__ w2,
                        const float* __restrict__ w3) {
    int i = blockIdx.x * 256 + threadIdx.x;
    if (i < C_ * 96) {
        int k = i / 96, j = i - k * 96;
        int br = j >> 5, co = j & 31;
        const float* w = br == 0 ? w1 : br == 1 ? w2 : w3;
        g_wAll[i] = w[co * C_ + k];
    }
}

// K1: three branch convs fused; emits bf16 split operands. grid 128, block 256.
__global__ void __launch_bounds__(256, 1) k1_conv(
    const float* __restrict__ x,
    const float* __restrict__ s1, const float* __restrict__ b1,
    const float* __restrict__ s2, const float* __restrict__ b2,
    const float* __restrict__ s3, const float* __restrict__ b3) {
    extern __shared__ float sm[];
    float* wAll = sm;
    float* sAll = sm + 24576;
    float* bAll = sAll + 96;
    int tid = threadIdx.x;
    const float4* wsrc = (const float4*)g_wAll;
#pragma unroll
    for (int s = 0; s < 24; s++) ((float4*)wAll)[tid + s * 256] = wsrc[tid + s * 256];
    if (tid < 96) {
        sAll[tid] = tid < 32 ? s1[tid] : tid < 64 ? s2[tid - 32] : s3[tid - 64];
        bAll[tid] = tid < 32 ? b1[tid] : tid < 64 ? b2[tid - 32] : b3[tid - 64];
    }
    __syncthreads();
    int gpos = blockIdx.x * 256 + tid;
    int b = gpos >> 12, m = gpos & (N_ - 1);
    const float* xp = x + b * C_ * N_ + m;
    u64 acc2[48];
#pragma unroll
    for (int i = 0; i < 48; i++) acc2[i] = 0ull;
#pragma unroll 2
    for (int k = 0; k < C_; k++) {
        float xv = __ldg(&xp[k * N_]);
        u64 xq = pack2(xv, xv);
        const ulonglong2* wk = (const ulonglong2*)&wAll[k * 96];
#pragma unroll
        for (int t = 0; t < 24; t++) {
            ulonglong2 wv = wk[t];
            acc2[2 * t]     = fma2(xq, wv.x, acc2[2 * t]);
            acc2[2 * t + 1] = fma2(xq, wv.y, acc2[2 * t + 1]);
        }
    }
#pragma unroll
    for (int br = 0; br < 2; br++) {
        unsigned hh[16], ll[16];
        float mulf = br ? L2E : 1.f;
#pragma unroll
        for (int p = 0; p < 16; p++) {
            float v0, v1;
            unpack2(acc2[br * 16 + p], v0, v1);
            float y0 = fmaf(v0, sAll[br * 32 + 2 * p],     bAll[br * 32 + 2 * p]);
            float y1 = fmaf(v1, sAll[br * 32 + 2 * p + 1], bAll[br * 32 + 2 * p + 1]);
            y0 = y0 * frcp(1.f + fexp2(-y0 * L2E)) * mulf;
            y1 = y1 * frcp(1.f + fexp2(-y1 * L2E)) * mulf;
            split2(make_float2(y0, y1), hh[p], ll[p]);
        }
        uint4* d = (uint4*)((br ? g_y2b : g_y1b) + (size_t)gpos * 64);
#pragma unroll
        for (int j = 0; j < 4; j++) d[j]     = make_uint4(hh[4 * j], hh[4 * j + 1], hh[4 * j + 2], hh[4 * j + 3]);
#pragma unroll
        for (int j = 0; j < 4; j++) d[4 + j] = make_uint4(ll[4 * j], ll[4 * j + 1], ll[4 * j + 2], ll[4 * j + 3]);
    }
#pragma unroll
    for (int p = 0; p < 16; p++) {
        float v0, v1;
        unpack2(acc2[32 + p], v0, v1);
        float y0 = fmaf(v0, sAll[64 + 2 * p],     bAll[64 + 2 * p]);
        float y1 = fmaf(v1, sAll[64 + 2 * p + 1], bAll[64 + 2 * p + 1]);
        y0 = y0 * frcp(1.f + fexp2(-y0 * L2E));
        y1 = y1 * frcp(1.f + fexp2(-y1 * L2E));
        size_t base = ((size_t)b * CI + 2 * p) * N_ + m;
        g_y3h[base]      = __float2bfloat16(y0);
        g_y3h[base + N_] = __float2bfloat16(y1);
    }
}

// K2t: softmax stats via mma.sync, ping-pong B. grid (32, B, NSPL2), block 128.
__global__ void __launch_bounds__(128) k2t() {
    __shared__ char SM[128 * STR + 2 * 64 * STR];
    char* An = SM;
    u32 sbA = smem_u32(An), sbB0 = sbA + 128 * STR;
    int tid = threadIdx.x, w = tid >> 5, L = tid & 31;
    int b = blockIdx.y, n0 = blockIdx.x * 128, hz = blockIdx.z;
    int mbase0 = hz * (N_ / NSPL2);
    constexpr int NT = N_ / NSPL2 / 64;   // 8 tiles
    {
        const uint4* s = (const uint4*)(g_y2b + ((size_t)b * N_ + n0 + tid) * 64);
        uint4* d = (uint4*)(An + tid * STR);
#pragma unroll
        for (int j = 0; j < 8; j++) d[j] = s[j];
    }
    __syncthreads();
    u32 Ah[2][2][4], Al[2][2][4];
    load_afrags(sbA, w, L, Ah, Al);

    int pr = tid >> 1, ph_ = tid & 1;
    uint4 pf[4];
    {
        const uint4* s = (const uint4*)(g_y1b + ((size_t)b * N_ + mbase0 + pr) * 64 + ph_ * 32);
#pragma unroll
        for (int j = 0; j < 4; j++) pf[j] = s[j];
    }

    float M[2][2], Z[2][2];
#pragma unroll
    for (int i = 0; i < 2; i++)
#pragma unroll
        for (int j = 0; j < 2; j++) { M[i][j] = -1.0e30f; Z[i][j] = 0.f; }

    for (int tt = 0; tt < NT; tt++) {
        u32 sbB = sbB0 + (u32)((tt & 1) * 64 * STR);
        {
            uint4* d = (uint4*)(SM + 128 * STR + (tt & 1) * 64 * STR + pr * STR + ph_ * 64);
            d[0] = pf[0]; d[1] = pf[1]; d[2] = pf[2]; d[3] = pf[3];
        }
        if (tt < NT - 1) {
            const uint4* s = (const uint4*)(g_y1b + ((size_t)b * N_ + mbase0 + (tt + 1) * 64 + pr) * 64 + ph_ * 32);
#pragma unroll
            for (int j = 0; j < 4; j++) pf[j] = s[j];
        }
        __syncthreads();
        float s_[2][8][4];
#pragma unroll
        for (int i = 0; i < 2; i++)
#pragma unroll
            for (int j = 0; j < 8; j++)
#pragma unroll
                for (int q = 0; q < 4; q++) s_[i][j][q] = 0.f;
#pragma unroll
        for (int j = 0; j < 8; j++) {
            u32 bb = sbB + (u32)((j * 8 + (L & 7)) * STR) + (u32)(((L >> 3) & 1) * 16);
            u32 Bh0[2], Bh1[2], Bl0[2], Bl1[2];
            ldsm2(Bh0, bb);      ldsm2(Bh1, bb + 32);
            ldsm2(Bl0, bb + 64); ldsm2(Bl1, bb + 96);
#pragma unroll
            for (int mb = 0; mb < 2; mb++) {
                mma16816(s_[mb][j], Ah[mb][0], Bh0); mma16816(s_[mb][j], Ah[mb][1], Bh1);
                mma16816(s_[mb][j], Al[mb][0], Bh0); mma16816(s_[mb][j], Al[mb][1], Bh1);
                mma16816(s_[mb][j], Ah[mb][0], Bl0); mma16816(s_[mb][j], Ah[mb][1], Bl1);
            }
        }
#pragma unroll
        for (int mb = 0; mb < 2; mb++)
#pragma unroll
            for (int rh = 0; rh < 2; rh++) {
                float mx = -1.0e30f;
#pragma unroll
                for (int j = 0; j < 8; j++)
                    mx = fmaxf(mx, fmaxf(s_[mb][j][rh * 2], s_[mb][j][rh * 2 + 1]));
                float nM = fmaxf(M[mb][rh], mx), ss = 0.f;
#pragma unroll
                for (int j = 0; j < 8; j++)
                    ss += fexp2(s_[mb][j][rh * 2] - nM) + fexp2(s_[mb][j][rh * 2 + 1] - nM);
                Z[mb][rh] = fmaf(Z[mb][rh], fexp2(M[mb][rh] - nM), ss);
                M[mb][rh] = nM;
            }
    }
#pragma unroll
    for (int mb = 0; mb < 2; mb++)
#pragma unroll
        for (int rh = 0; rh < 2; rh++) {
            float m = M[mb][rh], z = Z[mb][rh];
#pragma unroll
            for (int off = 1; off < 4; off <<= 1) {
                float mo = __shfl_xor_sync(0xffffffffu, m, off);
                float zo = __shfl_xor_sync(0xffffffffu, z, off);
                float nM = fmaxf(m, mo);
                z = fmaf(z, fexp2(m - nM), zo * fexp2(mo - nM));
                m = nM;
            }
            if ((L & 3) == 0)
                g_mz[(size_t)(hz * B_ + b) * N_ + n0 + w * 32 + mb * 16 + rh * 8 + (L >> 2)] =
                    make_float2(m, z);
        }
}

__global__ void k2b_merge() {
    int i = blockIdx.x * 256 + threadIdx.x;
    if (i < B_ * N_) {
        float M = -1.0e30f;
#pragma unroll
        for (int hz = 0; hz < NSPL2; hz++) M = fmaxf(M, g_mz[(size_t)hz * B_ * N_ + i].x);
        float Z = 0.f;
#pragma unroll
        for (int hz = 0; hz < NSPL2; hz++) {
            float2 p = g_mz[(size_t)hz * B_ * N_ + i];
            Z += p.y * fexp2(p.x - M);
        }
        g_alpha[i] = M + flog2(Z);
    }
}

// K3t: attention apply via mma.sync + FA2 register P, ping-pong Q/V/alpha.
// grid (32, B, NSPL), block 128.
__global__ void __launch_bounds__(128) k3t() {
    __shared__ char SM[128 * STR + 2 * 64 * STR + 2 * 32 * STR + 2 * 256 + 128];
    char* A1 = SM;
    const int QOFF = 128 * STR;
    const int VOFF = QOFF + 2 * 64 * STR;
    const int AOFF = VOFF + 2 * 32 * STR;
    u32 sbA = smem_u32(A1);
    int tid = threadIdx.x, w = tid >> 5, L = tid & 31;
    int b = blockIdx.y, m0 = blockIdx.x * 128, hz = blockIdx.z;
    int nbase0 = hz * (N_ / NSPL);
    constexpr int NT = N_ / NSPL / 64;
    {
        const uint4* s = (const uint4*)(g_y1b + ((size_t)b * N_ + m0 + tid) * 64);
        uint4* d = (uint4*)(A1 + tid * STR);
#pragma unroll
        for (int j = 0; j < 8; j++) d[j] = s[j];
    }
    __syncthreads();
    u32 Ah[2][2][4], Al[2][2][4];
    load_afrags(sbA, w, L, Ah, Al);

    float d2[2][4][4];
#pragma unroll
    for (int i = 0; i < 2; i++)
#pragma unroll
        for (int j = 0; j < 4; j++)
#pragma unroll
            for (int q = 0; q < 4; q++) d2[i][j][q] = 0.f;

    int qr = tid >> 1, qh = tid & 1, vci = tid >> 2, vq = tid & 3;
    uint4 qf[4], vf[2];
    {
        const uint4* s = (const uint4*)(g_y2b + ((size_t)b * N_ + nbase0 + qr) * 64 + qh * 32);
#pragma unroll
        for (int j = 0; j < 4; j++) qf[j] = s[j];
        const uint4* vh = (const uint4*)(g_y3h + ((size_t)b * CI + vci) * N_ + nbase0 + vq * 16);
        vf[0] = vh[0]; vf[1] = vh[1];
    }

    for (int tt = 0; tt < NT; tt++) {
        int cur = tt & 1;
        u32 sbQ = sbA + (u32)(QOFF + cur * 64 * STR);
        u32 sbVh = sbA + (u32)(VOFF + cur * 32 * STR);
        float* alp = (float*)(SM + AOFF + cur * 256);
        {
            uint4* d = (uint4*)(SM + QOFF + cur * 64 * STR + qr * STR + qh * 64);
            d[0] = qf[0]; d[1] = qf[1]; d[2] = qf[2]; d[3] = qf[3];
            uint4* dh = (uint4*)(SM + VOFF + cur * 32 * STR + vci * STR + vq * 32);
            dh[0] = vf[0]; dh[1] = vf[1];
            if (tid < 16)
                ((float4*)alp)[tid] = ((const float4*)(g_alpha + (size_t)b * N_ + nbase0 + tt * 64))[tid];
        }
        if (tt < NT - 1) {
            int n1 = nbase0 + (tt + 1) * 64;
            const uint4* s = (const uint4*)(g_y2b + ((size_t)b * N_ + n1 + qr) * 64 + qh * 32);
#pragma unroll
            for (int j = 0; j < 4; j++) qf[j] = s[j];
            const uint4* vh = (const uint4*)(g_y3h + ((size_t)b * CI + vci) * N_ + n1 + vq * 16);
            vf[0] = vh[0]; vf[1] = vh[1];
        }
        __syncthreads();
#pragma unroll
        for (int nbp = 0; nbp < 4; nbp++) {
            u32 Vhf[4][2];
#pragma unroll
            for (int cb = 0; cb < 4; cb++) {
                u32 va = (u32)((cb * 8 + (L & 7)) * STR) + (u32)(nbp * 32 + ((L >> 3) & 1) * 16);
                ldsm2(Vhf[cb], sbVh + va);
            }
            u32 Bh[2][2][2], Bl[2][2][2];
#pragma unroll
            for (int nb2 = 0; nb2 < 2; nb2++) {
                u32 qa = sbQ + (u32)(((nbp * 2 + nb2) * 8 + (L & 7)) * STR) + (u32)(((L >> 3) & 1) * 16);
                ldsm2(Bh[nb2][0], qa);      ldsm2(Bh[nb2][1], qa + 32);
                ldsm2(Bl[nb2][0], qa + 64); ldsm2(Bl[nb2][1], qa + 96);
            }
            float s_[2][2][4];
#pragma unroll
            for (int mb = 0; mb < 2; mb++)
#pragma unroll
                for (int nb2 = 0; nb2 < 2; nb2++) {
#pragma unroll
                    for (int q = 0; q < 4; q++) s_[mb][nb2][q] = 0.f;
                    mma16816(s_[mb][nb2], Ah[mb][0], Bh[nb2][0]); mma16816(s_[mb][nb2], Ah[mb][1], Bh[nb2][1]);
                    mma16816(s_[mb][nb2], Al[mb][0], Bh[nb2][0]); mma16816(s_[mb][nb2], Al[mb][1], Bh[nb2][1]);
                    mma16816(s_[mb][nb2], Ah[mb][0], Bl[nb2][0]); mma16816(s_[mb][nb2], Ah[mb][1], Bl[nb2][1]);
                }
            u32 ph[2][4], pl[2][4];
#pragma unroll
            for (int mb = 0; mb < 2; mb++)
#pragma unroll
                for (int nb2 = 0; nb2 < 2; nb2++) {
                    int cn = (nbp * 2 + nb2) * 8 + 2 * (L & 3);
                    float a0 = alp[cn], a1 = alp[cn + 1];
                    float e0 = fexp2(s_[mb][nb2][0] - a0), e1 = fexp2(s_[mb][nb2][1] - a1);
                    float e2 = fexp2(s_[mb][nb2][2] - a0), e3 = fexp2(s_[mb][nb2][3] - a1);
                    u32 h01 = cvt2(e0, e1), h23 = cvt2(e2, e3);
                    ph[mb][nb2 * 2] = h01; ph[mb][nb2 * 2 + 1] = h23;
                    pl[mb][nb2 * 2]     = cvt2(e0 - lo_f(h01), e1 - hi_f(h01));
                    pl[mb][nb2 * 2 + 1] = cvt2(e2 - lo_f(h23), e3 - hi_f(h23));
                }
#pragma unroll
            for (int mb = 0; mb < 2; mb++)
#pragma unroll
                for (int cb = 0; cb < 4; cb++) {
                    mma16816(d2[mb][cb], ph[mb], Vhf[cb]);
                    mma16816(d2[mb][cb], pl[mb], Vhf[cb]);
                }
        }
    }
    float* pp = g_part + (size_t)(hz * B_ + b) * CI * N_;
#pragma unroll
    for (int mb = 0; mb < 2; mb++)
#pragma unroll
        for (int cb = 0; cb < 4; cb++) {
            int row = m0 + w * 32 + mb * 16 + (L >> 2);
            int ci0 = cb * 8 + 2 * (L & 3);
            pp[(size_t)ci0 * N_ + row]           = d2[mb][cb][0];
            pp[(size_t)(ci0 + 1) * N_ + row]     = d2[mb][cb][1];
            pp[(size_t)ci0 * N_ + row + 8]       = d2[mb][cb][2];
            pp[(size_t)(ci0 + 1) * N_ + row + 8] = d2[mb][cb][3];
        }
}

// K4: reduce NSPL partials + final conv + BN + SiLU + residual. grid (64,8), block 128
__global__ void __launch_bounds__(128) k4_epi(
    const float* __restrict__ w4, const float* __restrict__ s4,
    const float* __restrict__ b4, const float* __restrict__ x,
    float* __restrict__ out) {
    __shared__ float Ys[32 * 68];
    __shared__ float W4t[32 * 260];
    __shared__ float s4s[256], b4s[256];
    int b = blockIdx.y, m0 = blockIdx.x * 64;
    int tid = threadIdx.x;
    int mg = tid & 15, cg = tid >> 4;
#pragma unroll
    for (int s = 0; s < 4; s++) {
        int idx = tid + s * 128;
        int ci = idx >> 4, off = (idx & 15) << 2;
        float4 u = make_float4(0.f, 0.f, 0.f, 0.f);
#pragma unroll
        for (int hz = 0; hz < NSPL; hz++) {
            const float4 v = *(const float4*)&g_part[(size_t)(hz * B_ + b) * CI * N_ + ci * N_ + m0 + off];
            u.x += v.x; u.y += v.y; u.z += v.z; u.w += v.w;
        }
        *(float4*)&Ys[ci * 68 + off] = u;
    }
    for (int idx = tid; idx < C_ * CI; idx += 128) {
        int co = idx >> 5, k = idx & 31;
        W4t[k * 260 + co] = w4[idx];
    }
    s4s[tid] = s4[tid]; s4s[tid + 128] = s4[tid + 128];
    b4s[tid] = b4[tid]; b4s[tid + 128] = b4[tid + 128];
    __syncthreads();
#pragma unroll
    for (int pass = 0; pass < 2; pass++) {
        int co0 = cg * 16 + pass * 128;
        u64 e2[16][2];
#pragma unroll
        for (int j = 0; j < 16; j++) { e2[j][0] = 0ull; e2[j][1] = 0ull; }
#pragma unroll 4
        for (int k = 0; k < CI; k++) {
            ulonglong2 ym = *(const ulonglong2*)&Ys[k * 68 + mg * 4];
#pragma unroll
            for (int q = 0; q < 4; q++) {
                float4 wq = *(const float4*)&W4t[k * 260 + co0 + q * 4];
                u64 w0 = pack2(wq.x, wq.x), w1 = pack2(wq.y, wq.y);
                u64 w2 = pack2(wq.z, wq.z), w3 = pack2(wq.w, wq.w);
                e2[q * 4 + 0][0] = fma2(w0, ym.x, e2[q * 4 + 0][0]);
                e2[q * 4 + 0][1] = fma2(w0, ym.y, e2[q * 4 + 0][1]);
                e2[q * 4 + 1][0] = fma2(w1, ym.x, e2[q * 4 + 1][0]);
                e2[q * 4 + 1][1] = fma2(w1, ym.y, e2[q * 4 + 1][1]);
                e2[q * 4 + 2][0] = fma2(w2, ym.x, e2[q * 4 + 2][0]);
                e2[q * 4 + 2][1] = fma2(w2, ym.y, e2[q * 4 + 2][1]);
                e2[q * 4 + 3][0] = fma2(w3, ym.x, e2[q * 4 + 3][0]);
                e2[q * 4 + 3][1] = fma2(w3, ym.y, e2[q * 4 + 3][1]);
            }
        }
#pragma unroll
        for (int j = 0; j < 16; j++) {
            int co = co0 + j;
            float sc = s4s[co], bi = b4s[co];
            float v0, v1, v2, v3;
            unpack2(e2[j][0], v0, v1); unpack2(e2[j][1], v2, v3);
            float y0 = fmaf(v0, sc, bi), y1 = fmaf(v1, sc, bi);
            float y2v = fmaf(v2, sc, bi), y3v = fmaf(v3, sc, bi);
            int off = b * C_ * N_ + co * N_ + m0 + mg * 4;
            float4 xr = *(const float4*)&x[off];
            float4 ov;
            ov.x = fmaf(y0,  frcp(1.f + fexp2(-y0 * L2E)),  xr.x);
            ov.y = fmaf(y1,  frcp(1.f + fexp2(-y1 * L2E)),  xr.y);
            ov.z = fmaf(y2v, frcp(1.f + fexp2(-y2v * L2E)), xr.z);
            ov.w = fmaf(y3v, frcp(1.f + fexp2(-y3v * L2E)), xr.w);
            *(float4*)&out[off] = ov;
        }
    }
}

extern "C" void kernel_launch(void* const* d_in, const int* in_sizes, int n_in,
                              void* d_out, int out_size) {
    (void)in_sizes; (void)n_in; (void)out_size;
    const float* x  = (const float*)d_in[0];
    const float* w1 = (const float*)d_in[1];
    const float* s1 = (const float*)d_in[2];
    const float* b1 = (const float*)d_in[3];
    const float* w2 = (const float*)d_in[4];
    const float* s2 = (const float*)d_in[5];
    const float* b2 = (const float*)d_in[6];
    const float* w3 = (const float*)d_in[7];
    const float* s3 = (const float*)d_in[8];
    const float* b3 = (const float*)d_in[9];
    const float* w4 = (const float*)d_in[10];
    const float* s4 = (const float*)d_in[11];
    const float* b4 = (const float*)d_in[12];
    float* out = (float*)d_out;

    cudaFuncSetAttribute(k1_conv, cudaFuncAttributeMaxDynamicSharedMemorySize, 99072);

    k0_prep<<<96, 256>>>(w1, w2, w3);
    k1_conv<<<128, 256, 99072>>>(x, s1, b1, s2, b2, s3, b3);
    k2t<<<dim3(32, B_, NSPL2), 128>>>();
    k2b_merge<<<(B_ * N_ + 255) / 256, 256>>>();
    k3t<<<dim3(32, B_, NSPL), 128>>>();
    k4_epi<<<dim3(64, B_), 128>>>(w4, s4, b4, x, out);
}

// round 16
// speedup vs baseline: 1.0452x; 1.0452x over previous
#include <cuda_runtime.h>
#include <cuda_bf16.h>
#include <cstdint>

#define DEV_INLINE __device__ __forceinline__
typedef unsigned long long u64;
typedef uint32_t u32;

constexpr int B_ = 8;
constexpr int C_ = 256;
constexpr int CI = 32;
constexpr int N_ = 4096;
constexpr int NSPL = 4;
constexpr float L2E = 1.4426950408889634f;
constexpr int STR = 144;   // smem operand row stride (bytes)

__device__ __align__(128) float g_alpha[B_ * N_];
__device__ __align__(128) float g_wAll[C_ * 96];
__device__ __align__(128) float g_part[NSPL * B_ * CI * N_];
__device__ __align__(128) float2 g_mz[NSPL * B_ * N_];
__device__ __align__(128) __nv_bfloat16 g_y1b[(size_t)B_ * N_ * 64];  // [pos][32hi|32lo]
__device__ __align__(128) __nv_bfloat16 g_y2b[(size_t)B_ * N_ * 64];  // pre-scaled log2e
__device__ __align__(128) __nv_bfloat16 g_y3h[(size_t)B_ * CI * N_];  // [ci][n] hi

DEV_INLINE float fexp2(float v) { float y; asm("ex2.approx.ftz.f32 %0, %1;" : "=f"(y) : "f"(v)); return y; }
DEV_INLINE float flog2(float v) { float y; asm("lg2.approx.ftz.f32 %0, %1;" : "=f"(y) : "f"(v)); return y; }
DEV_INLINE float frcp(float v)  { float y; asm("rcp.approx.ftz.f32 %0, %1;" : "=f"(y) : "f"(v)); return y; }
DEV_INLINE u64 pack2(float lo, float hi) {
    u64 r; asm("mov.b64 %0, {%1,%2};" : "=l"(r) : "r"(__float_as_uint(lo)), "r"(__float_as_uint(hi)));
    return r;
}
DEV_INLINE void unpack2(u64 v, float& lo, float& hi) {
    unsigned a, b; asm("mov.b64 {%0,%1}, %2;" : "=r"(a), "=r"(b) : "l"(v));
    lo = __uint_as_float(a); hi = __uint_as_float(b);
}
DEV_INLINE u64 fma2(u64 a, u64 b, u64 c) {
    u64 d; asm("fma.rn.f32x2 %0, %1, %2, %3;" : "=l"(d) : "l"(a), "l"(b), "l"(c));
    return d;
}
DEV_INLINE void split2(float2 f, unsigned& h, unsigned& l) {
    __nv_bfloat162 hb = __float22bfloat162_rn(f);
    h = *(unsigned*)&hb;
    float2 hf = __bfloat1622float2(hb);
    __nv_bfloat162 lb = __float22bfloat162_rn(make_float2(f.x - hf.x, f.y - hf.y));
    l = *(unsigned*)&lb;
}
DEV_INLINE u32 smem_u32(const void* p) {
    u32 a; asm("{ .reg .u64 t; cvta.to.shared.u64 t, %1; cvt.u32.u64 %0, t; }" : "=r"(a) : "l"(p));
    return a;
}
DEV_INLINE void ldsm4(u32* r, u32 a) {
    asm volatile("ldmatrix.sync.aligned.m8n8.x4.shared.b16 {%0,%1,%2,%3}, [%4];"
                 : "=r"(r[0]), "=r"(r[1]), "=r"(r[2]), "=r"(r[3]) : "r"(a));
}
DEV_INLINE void ldsm2(u32* r, u32 a) {
    asm volatile("ldmatrix.sync.aligned.m8n8.x2.shared.b16 {%0,%1}, [%2];"
                 : "=r"(r[0]), "=r"(r[1]) : "r"(a));
}
DEV_INLINE void mma16816(float* d, const u32* a, const u32* b) {
    asm volatile("mma.sync.aligned.m16n8k16.row.col.f32.bf16.bf16.f32 "
        "{%0,%1,%2,%3},{%4,%5,%6,%7},{%8,%9},{%0,%1,%2,%3};"
        : "+f"(d[0]), "+f"(d[1]), "+f"(d[2]), "+f"(d[3])
        : "r"(a[0]), "r"(a[1]), "r"(a[2]), "r"(a[3]), "r"(b[0]), "r"(b[1]));
}
DEV_INLINE u32 cvt2(float lo, float hi) {
    u32 r; asm("cvt.rn.bf16x2.f32 %0, %1, %2;" : "=r"(r) : "f"(hi), "f"(lo));
    return r;
}
DEV_INLINE float lo_f(u32 h) { return __uint_as_float(h << 16); }
DEV_INLINE float hi_f(u32 h) { return __uint_as_float(h & 0xffff0000u); }

DEV_INLINE void load_afrags(u32 base, int w, int L, u32 Ah[2][2][4], u32 Al[2][2][4]) {
#pragma unroll
    for (int mb = 0; mb < 2; mb++) {
        u32 a = base + (u32)((w * 32 + mb * 16 + (L & 15)) * STR) + (u32)((L >> 4) * 16);
#pragma unroll
        for (int k = 0; k < 2; k++) {
            ldsm4(Ah[mb][k], a + k * 32);
            ldsm4(Al[mb][k], a + 64 + k * 32);
        }
    }
}

// ---------------------------------------------------------------------------
__global__ void k0_prep(const float* __restrict__ w1, const float* __restrict__ w2,
                        const float* __restrict__ w3) {
    int i = blockIdx.x * 256 + threadIdx.x;
    if (i < C_ * 96) {
        int k = i / 96, j = i - k * 96;
        int br = j >> 5, co = j & 31;
        const float* w = br == 0 ? w1 : br == 1 ? w2 : w3;
        g_wAll[i] = w[co * C_ + k];
    }
}

// K1: three branch convs fused; emits bf16 split operands. grid 128, block 256.
__global__ void __launch_bounds__(256, 1) k1_conv(
    const float* __restrict__ x,
    const float* __restrict__ s1, const float* __restrict__ b1,
    const float* __restrict__ s2, const float* __restrict__ b2,
    const float* __restrict__ s3, const float* __restrict__ b3) {
    extern __shared__ float sm[];
    float* wAll = sm;
    float* sAll = sm + 24576;
    float* bAll = sAll + 96;
    int tid = threadIdx.x;
    const float4* wsrc = (const float4*)g_wAll;
#pragma unroll
    for (int s = 0; s < 24; s++) ((float4*)wAll)[tid + s * 256] = wsrc[tid + s * 256];
    if (tid < 96) {
        sAll[tid] = tid < 32 ? s1[tid] : tid < 64 ? s2[tid - 32] : s3[tid - 64];
        bAll[tid] = tid < 32 ? b1[tid] : tid < 64 ? b2[tid - 32] : b3[tid - 64];
    }
    __syncthreads();
    int gpos = blockIdx.x * 256 + tid;
    int b = gpos >> 12, m = gpos & (N_ - 1);
    const float* xp = x + b * C_ * N_ + m;
    u64 acc2[48];
#pragma unroll
    for (int i = 0; i < 48; i++) acc2[i] = 0ull;
#pragma unroll 2
    for (int k = 0; k < C_; k++) {
        float xv = __ldg(&xp[k * N_]);
        u64 xq = pack2(xv, xv);
        const ulonglong2* wk = (const ulonglong2*)&wAll[k * 96];
#pragma unroll
        for (int t = 0; t < 24; t++) {
            ulonglong2 wv = wk[t];
            acc2[2 * t]     = fma2(xq, wv.x, acc2[2 * t]);
            acc2[2 * t + 1] = fma2(xq, wv.y, acc2[2 * t + 1]);
        }
    }
#pragma unroll
    for (int br = 0; br < 2; br++) {
        unsigned hh[16], ll[16];
        float mulf = br ? L2E : 1.f;
#pragma unroll
        for (int p = 0; p < 16; p++) {
            float v0, v1;
            unpack2(acc2[br * 16 + p], v0, v1);
            float y0 = fmaf(v0, sAll[br * 32 + 2 * p],     bAll[br * 32 + 2 * p]);
            float y1 = fmaf(v1, sAll[br * 32 + 2 * p + 1], bAll[br * 32 + 2 * p + 1]);
            y0 = y0 * frcp(1.f + fexp2(-y0 * L2E)) * mulf;
            y1 = y1 * frcp(1.f + fexp2(-y1 * L2E)) * mulf;
            split2(make_float2(y0, y1), hh[p], ll[p]);
        }
        uint4* d = (uint4*)((br ? g_y2b : g_y1b) + (size_t)gpos * 64);
#pragma unroll
        for (int j = 0; j < 4; j++) d[j]     = make_uint4(hh[4 * j], hh[4 * j + 1], hh[4 * j + 2], hh[4 * j + 3]);
#pragma unroll
        for (int j = 0; j < 4; j++) d[4 + j] = make_uint4(ll[4 * j], ll[4 * j + 1], ll[4 * j + 2], ll[4 * j + 3]);
    }
#pragma unroll
    for (int p = 0; p < 16; p++) {
        float v0, v1;
        unpack2(acc2[32 + p], v0, v1);
        float y0 = fmaf(v0, sAll[64 + 2 * p],     bAll[64 + 2 * p]);
        float y1 = fmaf(v1, sAll[64 + 2 * p + 1], bAll[64 + 2 * p + 1]);
        y0 = y0 * frcp(1.f + fexp2(-y0 * L2E));
        y1 = y1 * frcp(1.f + fexp2(-y1 * L2E));
        size_t base = ((size_t)b * CI + 2 * p) * N_ + m;
        g_y3h[base]      = __float2bfloat16(y0);
        g_y3h[base + N_] = __float2bfloat16(y1);
    }
}

// K2t: softmax stats via mma.sync, ping-pong B. grid (32, B, NSPL), block 128.
__global__ void __launch_bounds__(128) k2t() {
    __shared__ char SM[128 * STR + 2 * 64 * STR];
    char* An = SM;
    u32 sbA = smem_u32(An), sbB0 = sbA + 128 * STR;
    int tid = threadIdx.x, w = tid >> 5, L = tid & 31;
    int b = blockIdx.y, n0 = blockIdx.x * 128, hz = blockIdx.z;
    int mbase0 = hz * (N_ / NSPL);
    constexpr int NT = N_ / NSPL / 64;   // 16 tiles
    {
        const uint4* s = (const uint4*)(g_y2b + ((size_t)b * N_ + n0 + tid) * 64);
        uint4* d = (uint4*)(An + tid * STR);
#pragma unroll
        for (int j = 0; j < 8; j++) d[j] = s[j];
    }
    __syncthreads();
    u32 Ah[2][2][4], Al[2][2][4];
    load_afrags(sbA, w, L, Ah, Al);

    int pr = tid >> 1, ph_ = tid & 1;
    uint4 pf[4];
    {
        const uint4* s = (const uint4*)(g_y1b + ((size_t)b * N_ + mbase0 + pr) * 64 + ph_ * 32);
#pragma unroll
        for (int j = 0; j < 4; j++) pf[j] = s[j];
    }

    float M[2][2], Z[2][2];
#pragma unroll
    for (int i = 0; i < 2; i++)
#pragma unroll
        for (int j = 0; j < 2; j++) { M[i][j] = -1.0e30f; Z[i][j] = 0.f; }

    for (int tt = 0; tt < NT; tt++) {
        u32 sbB = sbB0 + (u32)((tt & 1) * 64 * STR);
        {
            uint4* d = (uint4*)(SM + 128 * STR + (tt & 1) * 64 * STR + pr * STR + ph_ * 64);
            d[0] = pf[0]; d[1] = pf[1]; d[2] = pf[2]; d[3] = pf[3];
        }
        if (tt < NT - 1) {
            const uint4* s = (const uint4*)(g_y1b + ((size_t)b * N_ + mbase0 + (tt + 1) * 64 + pr) * 64 + ph_ * 32);
#pragma unroll
            for (int j = 0; j < 4; j++) pf[j] = s[j];
        }
        __syncthreads();
        float s_[2][8][4];
#pragma unroll
        for (int i = 0; i < 2; i++)
#pragma unroll
            for (int j = 0; j < 8; j++)
#pragma unroll
                for (int q = 0; q < 4; q++) s_[i][j][q] = 0.f;
#pragma unroll
        for (int j = 0; j < 8; j++) {
            u32 bb = sbB + (u32)((j * 8 + (L & 7)) * STR) + (u32)(((L >> 3) & 1) * 16);
            u32 Bh0[2], Bh1[2], Bl0[2], Bl1[2];
            ldsm2(Bh0, bb);      ldsm2(Bh1, bb + 32);
            ldsm2(Bl0, bb + 64); ldsm2(Bl1, bb + 96);
#pragma unroll
            for (int mb = 0; mb < 2; mb++) {
                mma16816(s_[mb][j], Ah[mb][0], Bh0); mma16816(s_[mb][j], Ah[mb][1], Bh1);
                mma16816(s_[mb][j], Al[mb][0], Bh0); mma16816(s_[mb][j], Al[mb][1], Bh1);
                mma16816(s_[mb][j], Ah[mb][0], Bl0); mma16816(s_[mb][j], Ah[mb][1], Bl1);
            }
        }
#pragma unroll
        for (int mb = 0; mb < 2; mb++)
#pragma unroll
            for (int rh = 0; rh < 2; rh++) {
                float mx = -1.0e30f;
#pragma unroll
                for (int j = 0; j < 8; j++)
                    mx = fmaxf(mx, fmaxf(s_[mb][j][rh * 2], s_[mb][j][rh * 2 + 1]));
                float nM = fmaxf(M[mb][rh], mx), ss = 0.f;
#pragma unroll
                for (int j = 0; j < 8; j++)
                    ss += fexp2(s_[mb][j][rh * 2] - nM) + fexp2(s_[mb][j][rh * 2 + 1] - nM);
                Z[mb][rh] = fmaf(Z[mb][rh], fexp2(M[mb][rh] - nM), ss);
                M[mb][rh] = nM;
            }
    }
#pragma unroll
    for (int mb = 0; mb < 2; mb++)
#pragma unroll
        for (int rh = 0; rh < 2; rh++) {
            float m = M[mb][rh], z = Z[mb][rh];
#pragma unroll
            for (int off = 1; off < 4; off <<= 1) {
                float mo = __shfl_xor_sync(0xffffffffu, m, off);
                float zo = __shfl_xor_sync(0xffffffffu, z, off);
                float nM = fmaxf(m, mo);
                z = fmaf(z, fexp2(m - nM), zo * fexp2(mo - nM));
                m = nM;
            }
            if ((L & 3) == 0)
                g_mz[(size_t)(hz * B_ + b) * N_ + n0 + w * 32 + mb * 16 + rh * 8 + (L >> 2)] =
                    make_float2(m, z);
        }
}

__global__ void k2b_merge() {
    int i = blockIdx.x * 256 + threadIdx.x;
    if (i < B_ * N_) {
        float2 p0 = g_mz[i];
        float2 p1 = g_mz[B_ * N_ + i];
        float2 p2 = g_mz[2 * B_ * N_ + i];
        float2 p3 = g_mz[3 * B_ * N_ + i];
        float M = fmaxf(fmaxf(p0.x, p1.x), fmaxf(p2.x, p3.x));
        float Z = p0.y * fexp2(p0.x - M) + p1.y * fexp2(p1.x - M)
                + p2.y * fexp2(p2.x - M) + p3.y * fexp2(p3.x - M);
        g_alpha[i] = M + flog2(Z);
    }
}

// K3t: attention apply via mma.sync + FA2 register P, ping-pong Q/V/alpha.
// Phase-ordered inner loop (S both halves -> exp both -> PV both).
// grid (32, B, NSPL), block 128.
__global__ void __launch_bounds__(128) k3t() {
    __shared__ char SM[128 * STR + 2 * 64 * STR + 2 * 32 * STR + 2 * 256 + 128];
    char* A1 = SM;
    const int QOFF = 128 * STR;
    const int VOFF = QOFF + 2 * 64 * STR;
    const int AOFF = VOFF + 2 * 32 * STR;
    u32 sbA = smem_u32(A1);
    int tid = threadIdx.x, w = tid >> 5, L = tid & 31;
    int b = blockIdx.y, m0 = blockIdx.x * 128, hz = blockIdx.z;
    int nbase0 = hz * (N_ / NSPL);
    constexpr int NT = N_ / NSPL / 64;
    {
        const uint4* s = (const uint4*)(g_y1b + ((size_t)b * N_ + m0 + tid) * 64);
        uint4* d = (uint4*)(A1 + tid * STR);
#pragma unroll
        for (int j = 0; j < 8; j++) d[j] = s[j];
    }
    __syncthreads();
    u32 Ah[2][2][4], Al[2][2][4];
    load_afrags(sbA, w, L, Ah, Al);

    float d2[2][4][4];
#pragma unroll
    for (int i = 0; i < 2; i++)
#pragma unroll
        for (int j = 0; j < 4; j++)
#pragma unroll
            for (int q = 0; q < 4; q++) d2[i][j][q] = 0.f;

    int qr = tid >> 1, qh = tid & 1, vci = tid >> 2, vq = tid & 3;
    uint4 qf[4], vf[2];
    {
        const uint4* s = (const uint4*)(g_y2b + ((size_t)b * N_ + nbase0 + qr) * 64 + qh * 32);
#pragma unroll
        for (int j = 0; j < 4; j++) qf[j] = s[j];
        const uint4* vh = (const uint4*)(g_y3h + ((size_t)b * CI + vci) * N_ + nbase0 + vq * 16);
        vf[0] = vh[0]; vf[1] = vh[1];
    }

    for (int tt = 0; tt < NT; tt++) {
        int cur = tt & 1;
        u32 sbQ = sbA + (u32)(QOFF + cur * 64 * STR);
        u32 sbVh = sbA + (u32)(VOFF + cur * 32 * STR);
        float* alp = (float*)(SM + AOFF + cur * 256);
        {
            uint4* d = (uint4*)(SM + QOFF + cur * 64 * STR + qr * STR + qh * 64);
            d[0] = qf[0]; d[1] = qf[1]; d[2] = qf[2]; d[3] = qf[3];
            uint4* dh = (uint4*)(SM + VOFF + cur * 32 * STR + vci * STR + vq * 32);
            dh[0] = vf[0]; dh[1] = vf[1];
            if (tid < 16)
                ((float4*)alp)[tid] = ((const float4*)(g_alpha + (size_t)b * N_ + nbase0 + tt * 64))[tid];
        }
        if (tt < NT - 1) {
            int n1 = nbase0 + (tt + 1) * 64;
            const uint4* s = (const uint4*)(g_y2b + ((size_t)b * N_ + n1 + qr) * 64 + qh * 32);
#pragma unroll
            for (int j = 0; j < 4; j++) qf[j] = s[j];
            const uint4* vh = (const uint4*)(g_y3h + ((size_t)b * CI + vci) * N_ + n1 + vq * 16);
            vf[0] = vh[0]; vf[1] = vh[1];
        }
        __syncthreads();
#pragma unroll
        for (int nbp = 0; nbp < 4; nbp++) {
            u32 Vhf[4][2];
#pragma unroll
            for (int cb = 0; cb < 4; cb++) {
                u32 va = (u32)((cb * 8 + (L & 7)) * STR) + (u32)(nbp * 32 + ((L >> 3) & 1) * 16);
                ldsm2(Vhf[cb], sbVh + va);
            }
            u32 Bh[2][2][2], Bl[2][2][2];
#pragma unroll
            for (int nb2 = 0; nb2 < 2; nb2++) {
                u32 qa = sbQ + (u32)(((nbp * 2 + nb2) * 8 + (L & 7)) * STR) + (u32)(((L >> 3) & 1) * 16);
                ldsm2(Bh[nb2][0], qa);      ldsm2(Bh[nb2][1], qa + 32);
                ldsm2(Bl[nb2][0], qa + 64); ldsm2(Bl[nb2][1], qa + 96);
            }
            float s_[2][2][4];
#pragma unroll
            for (int mb = 0; mb < 2; mb++)
#pragma unroll
                for (int nb2 = 0; nb2 < 2; nb2++) {
#pragma unroll
                    for (int q = 0; q < 4; q++) s_[mb][nb2][q] = 0.f;
                    mma16816(s_[mb][nb2], Ah[mb][0], Bh[nb2][0]); mma16816(s_[mb][nb2], Ah[mb][1], Bh[nb2][1]);
                    mma16816(s_[mb][nb2], Al[mb][0], Bh[nb2][0]); mma16816(s_[mb][nb2], Al[mb][1], Bh[nb2][1]);
                    mma16816(s_[mb][nb2], Ah[mb][0], Bl[nb2][0]); mma16816(s_[mb][nb2], Ah[mb][1], Bl[nb2][1]);
                }
            u32 ph[2][4], pl[2][4];
#pragma unroll
            for (int mb = 0; mb < 2; mb++)
#pragma unroll
                for (int nb2 = 0; nb2 < 2; nb2++) {
                    int cn = (nbp * 2 + nb2) * 8 + 2 * (L & 3);
                    float a0 = alp[cn], a1 = alp[cn + 1];
                    float e0 = fexp2(s_[mb][nb2][0] - a0), e1 = fexp2(s_[mb][nb2][1] - a1);
                    float e2 = fexp2(s_[mb][nb2][2] - a0), e3 = fexp2(s_[mb][nb2][3] - a1);
                    u32 h01 = cvt2(e0, e1), h23 = cvt2(e2, e3);
                    ph[mb][nb2 * 2] = h01; ph[mb][nb2 * 2 + 1] = h23;
                    pl[mb][nb2 * 2]     = cvt2(e0 - lo_f(h01), e1 - hi_f(h01));
                    pl[mb][nb2 * 2 + 1] = cvt2(e2 - lo_f(h23), e3 - hi_f(h23));
                }
#pragma unroll
            for (int mb = 0; mb < 2; mb++)
#pragma unroll
                for (int cb = 0; cb < 4; cb++) {
                    mma16816(d2[mb][cb], ph[mb], Vhf[cb]);
                    mma16816(d2[mb][cb], pl[mb], Vhf[cb]);
                }
        }
    }
    float* pp = g_part + (size_t)(hz * B_ + b) * CI * N_;
#pragma unroll
    for (int mb = 0; mb < 2; mb++)
#pragma unroll
        for (int cb = 0; cb < 4; cb++) {
            int row = m0 + w * 32 + mb * 16 + (L >> 2);
            int ci0 = cb * 8 + 2 * (L & 3);
            pp[(size_t)ci0 * N_ + row]           = d2[mb][cb][0];
            pp[(size_t)(ci0 + 1) * N_ + row]     = d2[mb][cb][1];
            pp[(size_t)ci0 * N_ + row + 8]       = d2[mb][cb][2];
            pp[(size_t)(ci0 + 1) * N_ + row + 8] = d2[mb][cb][3];
        }
}

// K4: reduce NSPL partials + final conv + BN + SiLU + residual. grid (64,8), block 128
__global__ void __launch_bounds__(128) k4_epi(
    const float* __restrict__ w4, const float* __restrict__ s4,
    const float* __restrict__ b4, const float* __restrict__ x,
    float* __restrict__ out) {
    __shared__ float Ys[32 * 68];
    __shared__ float W4t[32 * 260];
    __shared__ float s4s[256], b4s[256];
    int b = blockIdx.y, m0 = blockIdx.x * 64;
    int tid = threadIdx.x;
    int mg = tid & 15, cg = tid >> 4;
#pragma unroll
    for (int s = 0; s < 4; s++) {
        int idx = tid + s * 128;
        int ci = idx >> 4, off = (idx & 15) << 2;
        float4 u = make_float4(0.f, 0.f, 0.f, 0.f);
#pragma unroll
        for (int hz = 0; hz < NSPL; hz++) {
            // read-once partials: streaming loads (keep x resident in L2)
            const float4 v = __ldcs((const float4*)&g_part[(size_t)(hz * B_ + b) * CI * N_ + ci * N_ + m0 + off]);
            u.x += v.x; u.y += v.y; u.z += v.z; u.w += v.w;
        }
        *(float4*)&Ys[ci * 68 + off] = u;
    }
    for (int idx = tid; idx < C_ * CI; idx += 128) {
        int co = idx >> 5, k = idx & 31;
        W4t[k * 260 + co] = w4[idx];
    }
    s4s[tid] = s4[tid]; s4s[tid + 128] = s4[tid + 128];
    b4s[tid] = b4[tid]; b4s[tid + 128] = b4[tid + 128];
    __syncthreads();
#pragma unroll
    for (int pass = 0; pass < 2; pass++) {
        int co0 = cg * 16 + pass * 128;
        u64 e2[16][2];
#pragma unroll
        for (int j = 0; j < 16; j++) { e2[j][0] = 0ull; e2[j][1] = 0ull; }
#pragma unroll 4
        for (int k = 0; k < CI; k++) {
            ulonglong2 ym = *(const ulonglong2*)&Ys[k * 68 + mg * 4];
#pragma unroll
            for (int q = 0; q < 4; q++) {
                float4 wq = *(const float4*)&W4t[k * 260 + co0 + q * 4];
                u64 w0 = pack2(wq.x, wq.x), w1 = pack2(wq.y, wq.y);
                u64 w2 = pack2(wq.z, wq.z), w3 = pack2(wq.w, wq.w);
                e2[q * 4 + 0][0] = fma2(w0, ym.x, e2[q * 4 + 0][0]);
                e2[q * 4 + 0][1] = fma2(w0, ym.y, e2[q * 4 + 0][1]);
                e2[q * 4 + 1][0] = fma2(w1, ym.x, e2[q * 4 + 1][0]);
                e2[q * 4 + 1][1] = fma2(w1, ym.y, e2[q * 4 + 1][1]);
                e2[q * 4 + 2][0] = fma2(w2, ym.x, e2[q * 4 + 2][0]);
                e2[q * 4 + 2][1] = fma2(w2, ym.y, e2[q * 4 + 2][1]);
                e2[q * 4 + 3][0] = fma2(w3, ym.x, e2[q * 4 + 3][0]);
                e2[q * 4 + 3][1] = fma2(w3, ym.y, e2[q * 4 + 3][1]);
            }
        }
#pragma unroll
        for (int j = 0; j < 16; j++) {
            int co = co0 + j;
            float sc = s4s[co], bi = b4s[co];
            float v0, v1, v2, v3;
            unpack2(e2[j][0], v0, v1); unpack2(e2[j][1], v2, v3);
            float y0 = fmaf(v0, sc, bi), y1 = fmaf(v1, sc, bi);
            float y2v = fmaf(v2, sc, bi), y3v = fmaf(v3, sc, bi);
            int off = b * C_ * N_ + co * N_ + m0 + mg * 4;
            float4 xr = *(const float4*)&x[off];
            float4 ov;
            ov.x = fmaf(y0,  frcp(1.f + fexp2(-y0 * L2E)),  xr.x);
            ov.y = fmaf(y1,  frcp(1.f + fexp2(-y1 * L2E)),  xr.y);
            ov.z = fmaf(y2v, frcp(1.f + fexp2(-y2v * L2E)), xr.z);
            ov.w = fmaf(y3v, frcp(1.f + fexp2(-y3v * L2E)), xr.w);
            __stcs((float4*)&out[off], ov);   // write-once: streaming store
        }
    }
}

extern "C" void kernel_launch(void* const* d_in, const int* in_sizes, int n_in,
                              void* d_out, int out_size) {
    (void)in_sizes; (void)n_in; (void)out_size;
    const float* x  = (const float*)d_in[0];
    const float* w1 = (const float*)d_in[1];
    const float* s1 = (const float*)d_in[2];
    const float* b1 = (const float*)d_in[3];
    const float* w2 = (const float*)d_in[4];
    const float* s2 = (const float*)d_in[5];
    const float* b2 = (const float*)d_in[6];
    const float* w3 = (const float*)d_in[7];
    const float* s3 = (const float*)d_in[8];
    const float* b3 = (const float*)d_in[9];
    const float* w4 = (const float*)d_in[10];
    const float* s4 = (const float*)d_in[11];
    const float* b4 = (const float*)d_in[12];
    float* out = (float*)d_out;

    cudaFuncSetAttribute(k1_conv, cudaFuncAttributeMaxDynamicSharedMemorySize, 99072);

    k0_prep<<<96, 256>>>(w1, w2, w3);
    k1_conv<<<128, 256, 99072>>>(x, s1, b1, s2, b2, s3, b3);
    k2t<<<dim3(32, B_, NSPL), 128>>>();
    k2b_merge<<<(B_ * N_ + 255) / 256, 256>>>();
    k3t<<<dim3(32, B_, NSPL), 128>>>();
    k4_epi<<<dim3(64, B_), 128>>>(w4, s4, b4, x, out);
}